// round 1
// baseline (speedup 1.0000x reference)
#include <cuda_runtime.h>
#include <cuda_bf16.h>
#include <math.h>

// FFMCell: new_state = state * gamma(t) + x, gamma = exp((-|a| + i b) * t)
// Shapes: T=4096, TRACE=64, CTX=64 (taken from in_sizes at runtime).
// Output: stack([new_re, new_im], axis=-1) flattened, optionally followed by
// the (j + i) counter vector (length T) if out_size has room for it.

__global__ void __launch_bounds__(256, 8) ffm_cell_kernel(
    const float4* __restrict__ sre,
    const float4* __restrict__ sim,
    const float4* __restrict__ xre,
    const float4* __restrict__ xim,
    const float* __restrict__ a,
    const float* __restrict__ b,
    const int* __restrict__ ivec,
    const int* __restrict__ jvec,
    float* __restrict__ out,
    float* __restrict__ out_tail,   // nullptr if no tail
    int trace, int ctx)
{
    const int t = blockIdx.x;
    const int tid = threadIdx.x;

    // Shared per-t factors: decay[trace], cos/sin[ctx]  (trace=ctx=64 here)
    __shared__ float s_decay[64];
    __shared__ float s_cos[64];
    __shared__ float s_sin[64];

    const float tf = (float)jvec[t];

    if (tid < 64) {
        // decay(t, tr) = exp(-|a[tr]| * t)
        s_decay[tid] = expf(-fabsf(a[tid]) * tf);
    } else if (tid < 128) {
        int c = tid - 64;
        float th = b[c] * tf;        // same fp32 product as the JAX reference
        float sn, cs;
        sincosf(th, &sn, &cs);
        s_sin[c] = sn;
        s_cos[c] = cs;
    }
    if (tid == 0 && out_tail != nullptr) {
        out_tail[t] = (float)(jvec[t] + ivec[t]);
    }
    __syncthreads();

    // Per-t tile: trace*ctx = 4096 floats = 1024 float4 groups.
    // 256 threads x 4 iterations. Each float4 group covers 4 consecutive ctx.
    const size_t base4 = (size_t)t * 1024;

    float4* __restrict__ out4 = reinterpret_cast<float4*>(out);

    #pragma unroll
    for (int it = 0; it < 4; ++it) {
        const int g = tid + it * 256;          // 0..1023
        const int tr = g >> 4;                 // 16 float4 per ctx-row of 64
        const int c0 = (g & 15) << 2;          // starting ctx index

        const size_t idx = base4 + g;
        const float4 sr = sre[idx];
        const float4 si = sim[idx];
        const float4 xr = xre[idx];
        const float4 xi = xim[idx];

        const float d = s_decay[tr];

        const float gr0 = d * s_cos[c0 + 0], gi0 = d * s_sin[c0 + 0];
        const float gr1 = d * s_cos[c0 + 1], gi1 = d * s_sin[c0 + 1];
        const float gr2 = d * s_cos[c0 + 2], gi2 = d * s_sin[c0 + 2];
        const float gr3 = d * s_cos[c0 + 3], gi3 = d * s_sin[c0 + 3];

        float4 o0, o1;
        // element 0
        o0.x = fmaf(sr.x, gr0, fmaf(-si.x, gi0, xr.x));
        o0.y = fmaf(sr.x, gi0, fmaf( si.x, gr0, xi.x));
        // element 1
        o0.z = fmaf(sr.y, gr1, fmaf(-si.y, gi1, xr.y));
        o0.w = fmaf(sr.y, gi1, fmaf( si.y, gr1, xi.y));
        // element 2
        o1.x = fmaf(sr.z, gr2, fmaf(-si.z, gi2, xr.z));
        o1.y = fmaf(sr.z, gi2, fmaf( si.z, gr2, xi.z));
        // element 3
        o1.z = fmaf(sr.w, gr3, fmaf(-si.w, gi3, xr.w));
        o1.w = fmaf(sr.w, gi3, fmaf( si.w, gr3, xi.w));

        // Output: (re, im) interleaved -> 8 consecutive floats = 2 float4
        const size_t oidx = 2 * idx;
        out4[oidx + 0] = o0;
        out4[oidx + 1] = o1;
    }
}

extern "C" void kernel_launch(void* const* d_in, const int* in_sizes, int n_in,
                              void* d_out, int out_size)
{
    const float4* sre = (const float4*)d_in[0];
    const float4* sim = (const float4*)d_in[1];
    const float4* xre = (const float4*)d_in[2];
    const float4* xim = (const float4*)d_in[3];
    const float*  a   = (const float*)d_in[4];
    const float*  b   = (const float*)d_in[5];
    const int*    iv  = (const int*)d_in[6];
    const int*    jv  = (const int*)d_in[7];

    const int trace = in_sizes[4];          // 64
    const int ctx   = in_sizes[5];          // 64
    const int T     = in_sizes[6];          // 4096
    const long long N = (long long)in_sizes[0];   // T*trace*ctx

    float* out = (float*)d_out;
    float* out_tail = nullptr;
    if ((long long)out_size > 2LL * N) {
        out_tail = out + 2LL * N;
    }

    ffm_cell_kernel<<<T, 256>>>(sre, sim, xre, xim, a, b, iv, jv,
                                out, out_tail, trace, ctx);
}

// round 2
// speedup vs baseline: 1.5118x; 1.5118x over previous
#include <cuda_runtime.h>
#include <cuda_bf16.h>
#include <math.h>

// FFMCell: new_state = state * gamma(t) + x, gamma = exp((-|a| + i b) * t)
// T=4096, TRACE=64, CTX=64 (runtime from in_sizes).
// Output: stack([new_re,new_im], -1) flattened; optional (j+i) tail if room.
//
// R2 change: front-batch all 16 LDG.128s per thread BEFORE the
// transcendental + smem + barrier prologue, so DRAM traffic streams while
// MUFU latency drains. launch_bounds(256,3) -> <=85 regs, 24 warps/SM.

__global__ void __launch_bounds__(256, 3) ffm_cell_kernel(
    const float4* __restrict__ sre,
    const float4* __restrict__ sim,
    const float4* __restrict__ xre,
    const float4* __restrict__ xim,
    const float* __restrict__ a,
    const float* __restrict__ b,
    const int* __restrict__ ivec,
    const int* __restrict__ jvec,
    float* __restrict__ out,
    float* __restrict__ out_tail)   // nullptr if no tail
{
    const int t = blockIdx.x;
    const int tid = threadIdx.x;

    __shared__ float s_decay[64];
    __shared__ float s_cos[64];
    __shared__ float s_sin[64];

    const size_t base4 = (size_t)t * 1024;

    // ---- Phase 0: issue ALL global loads first (independent of smem) ----
    float4 sr[4], si[4], xr[4], xi[4];
    #pragma unroll
    for (int it = 0; it < 4; ++it) {
        const size_t idx = base4 + tid + it * 256;
        sr[it] = sre[idx];
        si[it] = sim[idx];
        xr[it] = xre[idx];
        xi[it] = xim[idx];
    }

    // ---- Phase 1: per-t factors into smem (overlaps with loads in flight) --
    const float tf = (float)__ldg(&jvec[t]);

    if (tid < 64) {
        s_decay[tid] = expf(-fabsf(a[tid]) * tf);
    } else if (tid < 128) {
        const int c = tid - 64;
        const float th = b[c] * tf;     // same fp32 product as reference
        float sn, cs;
        sincosf(th, &sn, &cs);
        s_sin[c] = sn;
        s_cos[c] = cs;
    } else if (tid == 128 && out_tail != nullptr) {
        out_tail[t] = (float)(__ldg(&jvec[t]) + __ldg(&ivec[t]));
    }
    __syncthreads();

    // ---- Phase 2: compute + store --------------------------------------
    float4* __restrict__ out4 = reinterpret_cast<float4*>(out);

    #pragma unroll
    for (int it = 0; it < 4; ++it) {
        const int g  = tid + it * 256;        // 0..1023
        const int tr = g >> 4;                // trace row (16 quads per row)
        const int c0 = (g & 15) << 2;         // ctx start

        const float d = s_decay[tr];

        const float gr0 = d * s_cos[c0 + 0], gi0 = d * s_sin[c0 + 0];
        const float gr1 = d * s_cos[c0 + 1], gi1 = d * s_sin[c0 + 1];
        const float gr2 = d * s_cos[c0 + 2], gi2 = d * s_sin[c0 + 2];
        const float gr3 = d * s_cos[c0 + 3], gi3 = d * s_sin[c0 + 3];

        float4 o0, o1;
        o0.x = fmaf(sr[it].x, gr0, fmaf(-si[it].x, gi0, xr[it].x));
        o0.y = fmaf(sr[it].x, gi0, fmaf( si[it].x, gr0, xi[it].x));
        o0.z = fmaf(sr[it].y, gr1, fmaf(-si[it].y, gi1, xr[it].y));
        o0.w = fmaf(sr[it].y, gi1, fmaf( si[it].y, gr1, xi[it].y));
        o1.x = fmaf(sr[it].z, gr2, fmaf(-si[it].z, gi2, xr[it].z));
        o1.y = fmaf(sr[it].z, gi2, fmaf( si[it].z, gr2, xi[it].z));
        o1.z = fmaf(sr[it].w, gr3, fmaf(-si[it].w, gi3, xr[it].w));
        o1.w = fmaf(sr[it].w, gi3, fmaf( si[it].w, gr3, xi[it].w));

        const size_t oidx = 2 * (base4 + g);
        out4[oidx + 0] = o0;
        out4[oidx + 1] = o1;
    }
}

extern "C" void kernel_launch(void* const* d_in, const int* in_sizes, int n_in,
                              void* d_out, int out_size)
{
    const float4* sre = (const float4*)d_in[0];
    const float4* sim = (const float4*)d_in[1];
    const float4* xre = (const float4*)d_in[2];
    const float4* xim = (const float4*)d_in[3];
    const float*  a   = (const float*)d_in[4];
    const float*  b   = (const float*)d_in[5];
    const int*    iv  = (const int*)d_in[6];
    const int*    jv  = (const int*)d_in[7];

    const int T = in_sizes[6];                      // 4096
    const long long N = (long long)in_sizes[0];     // T*TRACE*CTX

    float* out = (float*)d_out;
    float* out_tail = nullptr;
    if ((long long)out_size > 2LL * N) {
        out_tail = out + 2LL * N;
    }

    ffm_cell_kernel<<<T, 256>>>(sre, sim, xre, xim, a, b, iv, jv,
                                out, out_tail);
}